// round 12
// baseline (speedup 1.0000x reference)
#include <cuda_runtime.h>
#include <cstdint>

#define B_  2048
#define NI_ 15
#define MI_ 3

// ---------------------------------------------------------------------------
// smem float-offsets (SMEM_BYTES = 191488):
//   fsk [256 k][132 row] f32 @ 0                          (135168 B)
//   WB: 2 bufs x [2 hl][8 k][264] f32 @ 33792f            (33792 B)
//   AB: 2 bufs x [2 hl][8 k][132] f32 @ 42240f            (16896 B)
//   phase-2 aliases WB/AB: Cs@33792f lKs@37952f Ts@42112f (each 64x65)
//   smalls from 46464f
// ---------------------------------------------------------------------------
#define FS_STRIDE   132
#define WB_OFF_F    33792
#define WB_BUF_F    4224
#define WB_HL_F     2112
#define AB_OFF_F    42240
#define AB_BUF_F    2112
#define AB_HL_F     1056
#define CS_OFF_F    33792
#define LKS_OFF_F   37952
#define TS_OFF_F    42112
#define B1S_OFF_F   46464
#define B2S_OFF_F   46720
#define LA_OFF_F    46976
#define LB_OFF_F    47040
#define RSA_OFF_F   47104
#define RSB_OFF_F   47168
#define LMQ_OFF_F   47232
#define LMR_OFF_F   47296
#define RED_OFF_F   47360
#define SMEM_BYTES  191488

// W pre-split tf32 hi/lo, k-major: g_Ws[layer][hl][k][e], 1 MB (L2-resident).
__device__ float g_Ws[2 * 2 * 256 * 256];

// ---------------------------------------------------------------------------
// helpers
// ---------------------------------------------------------------------------
__device__ __forceinline__ void tf32split(float x, uint32_t& hi, uint32_t& lo) {
    asm("cvt.rna.tf32.f32 %0, %1;" : "=r"(hi) : "f"(x));
    float d = x - __uint_as_float(hi);
    asm("cvt.rna.tf32.f32 %0, %1;" : "=r"(lo) : "f"(d));
}
__device__ __forceinline__ void mma8(float* d, const uint32_t* a, const uint32_t* b) {
    asm volatile(
        "mma.sync.aligned.m16n8k8.row.col.f32.tf32.tf32.f32 "
        "{%0,%1,%2,%3}, {%4,%5,%6,%7}, {%8,%9}, {%0,%1,%2,%3};"
        : "+f"(d[0]), "+f"(d[1]), "+f"(d[2]), "+f"(d[3])
        : "r"(a[0]), "r"(a[1]), "r"(a[2]), "r"(a[3]), "r"(b[0]), "r"(b[1]));
}
__device__ __forceinline__ unsigned long long pack2(float lo, float hi) {
    unsigned long long r;
    asm("mov.b64 %0, {%1,%2};" : "=l"(r) : "f"(lo), "f"(hi));
    return r;
}
__device__ __forceinline__ void unpack2(unsigned long long v, float& lo, float& hi) {
    asm("mov.b64 {%0,%1}, %2;" : "=f"(lo), "=f"(hi) : "l"(v));
}
__device__ __forceinline__ unsigned long long fma2(unsigned long long a,
                                                   unsigned long long b,
                                                   unsigned long long c) {
    unsigned long long d;
    asm("fma.rn.f32x2 %0, %1, %2, %3;" : "=l"(d) : "l"(a), "l"(b), "l"(c));
    return d;
}

// ---------------------------------------------------------------------------
// W prep: g_Ws[L][hl][k][e] = tf32 hi/lo of W_L[e][k]
// ---------------------------------------------------------------------------
__global__ void wprep_kernel(const float* __restrict__ W1, const float* __restrict__ W2) {
    for (int i = blockIdx.x * 256 + threadIdx.x; i < 262144; i += gridDim.x * 256) {
        int L  = i >> 17;
        int hl = (i >> 16) & 1;
        int k  = (i >> 8) & 255;
        int e  = i & 255;
        float w = (L ? W2 : W1)[(size_t)e * 256 + k];
        uint32_t hi, lo;
        tf32split(w, hi, lo);
        g_Ws[i] = __uint_as_float(hl ? lo : hi);
    }
}

// ---------------------------------------------------------------------------
// Fused kernel: one block per batch, 512 threads, tf32 3-pass MMA MLP.
// ---------------------------------------------------------------------------
__global__ void __launch_bounds__(512, 1) fused_kernel(
    const float* __restrict__ sq, const float* __restrict__ sr,
    const float* __restrict__ mq, const float* __restrict__ mr,
    const float* __restrict__ b1, const float* __restrict__ b2,
    float* __restrict__ out)
{
    extern __shared__ float sm[];
    float* fsk = sm;
    float* b1s = sm + B1S_OFF_F;
    float* b2s = sm + B2S_OFF_F;
    float* la  = sm + LA_OFF_F;
    float* lb  = sm + LB_OFF_F;
    float* rsA = sm + RSA_OFF_F;
    float* rsB = sm + RSB_OFF_F;
    float* lmq = sm + LMQ_OFF_F;
    float* lmr = sm + LMR_OFF_F;
    float* red = sm + RED_OFF_F;
    float* Cs  = sm + CS_OFF_F;
    float* lKs = sm + LKS_OFF_F;
    float* Ts  = sm + TS_OFF_F;

    const int t   = threadIdx.x;
    const int l   = t & 31;
    const int w   = t >> 5;
    const int mg  = w & 1;               // rows 64*mg .. +63
    const int ng  = w >> 1;              // cols 32*ng .. +31 (0..7)
    const int lg  = l >> 2;              // 0..7
    const int tig = l & 3;               // 0..3
    const int b   = blockIdx.x;

    float* out_sig = out;
    float* out_T   = out + B_;
    float* out_C   = out_T + (size_t)B_ * 64 * 64;
    float* out_c   = out_C + (size_t)B_ * 64 * 64;

    // ---- load x coalesced, transpose into fsk[k][row] -----------------------
    {
        #pragma unroll
        for (int i = 0; i < 16; ++i) {
            int idx = t + i * 512;           // float4 index, 8192 total
            int row = idx >> 6;
            int d4  = (idx & 63) << 2;
            const float* src = (row < 64)
                ? sq + ((size_t)b * 64 + row) * 256
                : sr + ((size_t)b * 64 + (row - 64)) * 256;
            float4 v = *(const float4*)(src + d4);
            fsk[(d4 + 0) * FS_STRIDE + row] = v.x;
            fsk[(d4 + 1) * FS_STRIDE + row] = v.y;
            fsk[(d4 + 2) * FS_STRIDE + row] = v.z;
            fsk[(d4 + 3) * FS_STRIDE + row] = v.w;
        }
        if (t < 256) b1s[t] = b1[t];
        else         b2s[t - 256] = b2[t - 256];
    }
    __syncthreads();

    // ---- 2-layer MLP via 3xTF32 mma.sync, pre-split operands ----------------
    float acc[4][4][4];

    for (int layer = 0; layer < 2; ++layer) {
        const float* Wsrc = g_Ws + (size_t)layer * 131072;  // [2 hl][256][256]

        #pragma unroll
        for (int m = 0; m < 4; ++m)
            #pragma unroll
            for (int n = 0; n < 4; ++n)
                #pragma unroll
                for (int j = 0; j < 4; ++j) acc[m][n][j] = 0.f;

        // prologue: stage W chunk 0 + split A chunk 0 into buf 0
        {
            float* wb = sm + WB_OFF_F;
            #pragma unroll
            for (int i = 0; i < 2; ++i) {
                int idx = t + i * 512;           // 1024 float4
                int hl = idx >> 9, kk = (idx >> 6) & 7, e4 = (idx & 63) << 2;
                *(float4*)&wb[hl * WB_HL_F + kk * 264 + e4] =
                    *(const float4*)&Wsrc[(hl * 256 + kk) * 256 + e4];
            }
            float* ab = sm + AB_OFF_F;
            #pragma unroll
            for (int i = 0; i < 2; ++i) {
                int idx = t + i * 512;           // 1024 elements
                int kk = idx >> 7, row = idx & 127;
                uint32_t hi, lo;
                tf32split(fsk[kk * FS_STRIDE + row], hi, lo);
                ab[kk * 132 + row]           = __uint_as_float(hi);
                ab[AB_HL_F + kk * 132 + row] = __uint_as_float(lo);
            }
        }
        __syncthreads();

        for (int c = 0; c < 32; ++c) {
            const int buf = c & 1, nb = buf ^ 1;
            if (c < 31) {
                float* wb = sm + WB_OFF_F + nb * WB_BUF_F;
                #pragma unroll
                for (int i = 0; i < 2; ++i) {
                    int idx = t + i * 512;
                    int hl = idx >> 9, kk = (idx >> 6) & 7, e4 = (idx & 63) << 2;
                    *(float4*)&wb[hl * WB_HL_F + kk * 264 + e4] =
                        *(const float4*)&Wsrc[(hl * 256 + (c + 1) * 8 + kk) * 256 + e4];
                }
                float* ab = sm + AB_OFF_F + nb * AB_BUF_F;
                #pragma unroll
                for (int i = 0; i < 2; ++i) {
                    int idx = t + i * 512;
                    int kk = idx >> 7, row = idx & 127;
                    uint32_t hi, lo;
                    tf32split(fsk[((c + 1) * 8 + kk) * FS_STRIDE + row], hi, lo);
                    ab[kk * 132 + row]           = __uint_as_float(hi);
                    ab[AB_HL_F + kk * 132 + row] = __uint_as_float(lo);
                }
            }
            // compute chunk c (8 k = one mma k-step)
            {
                const float* wb = sm + WB_OFF_F + buf * WB_BUF_F;
                const float* ab = sm + AB_OFF_F + buf * AB_BUF_F;
                uint32_t whi[4][2], wlo[4][2];
                #pragma unroll
                for (int nt = 0; nt < 4; ++nt) {
                    int col = ng * 32 + nt * 8 + lg;
                    whi[nt][0] = __float_as_uint(wb[tig * 264 + col]);
                    whi[nt][1] = __float_as_uint(wb[(tig + 4) * 264 + col]);
                    wlo[nt][0] = __float_as_uint(wb[WB_HL_F + tig * 264 + col]);
                    wlo[nt][1] = __float_as_uint(wb[WB_HL_F + (tig + 4) * 264 + col]);
                }
                #pragma unroll
                for (int m = 0; m < 4; ++m) {
                    int r0 = mg * 64 + m * 16 + lg;
                    uint32_t ahi[4], alo[4];
                    ahi[0] = __float_as_uint(ab[tig * 132 + r0]);
                    ahi[1] = __float_as_uint(ab[tig * 132 + r0 + 8]);
                    ahi[2] = __float_as_uint(ab[(tig + 4) * 132 + r0]);
                    ahi[3] = __float_as_uint(ab[(tig + 4) * 132 + r0 + 8]);
                    alo[0] = __float_as_uint(ab[AB_HL_F + tig * 132 + r0]);
                    alo[1] = __float_as_uint(ab[AB_HL_F + tig * 132 + r0 + 8]);
                    alo[2] = __float_as_uint(ab[AB_HL_F + (tig + 4) * 132 + r0]);
                    alo[3] = __float_as_uint(ab[AB_HL_F + (tig + 4) * 132 + r0 + 8]);
                    #pragma unroll
                    for (int nt = 0; nt < 4; ++nt) {
                        mma8(acc[m][nt], ahi, whi[nt]);
                        mma8(acc[m][nt], alo, whi[nt]);
                        mma8(acc[m][nt], ahi, wlo[nt]);
                    }
                }
            }
            __syncthreads();
        }

        // ---- epilogue -> fsk k-major ----------------------------------------
        const float* bp = layer ? b2s : b1s;
        const bool relu = (layer == 0);
        #pragma unroll
        for (int m = 0; m < 4; ++m) {
            const int r0 = mg * 64 + m * 16 + lg;
            #pragma unroll
            for (int nt = 0; nt < 4; ++nt) {
                const int cc = ng * 32 + nt * 8 + 2 * tig;
                float bc0 = bp[cc], bc1 = bp[cc + 1];
                float v0 = acc[m][nt][0] + bc0;
                float v1 = acc[m][nt][1] + bc1;
                float v2 = acc[m][nt][2] + bc0;
                float v3 = acc[m][nt][3] + bc1;
                if (relu) {
                    v0 = fmaxf(v0, 0.f); v1 = fmaxf(v1, 0.f);
                    v2 = fmaxf(v2, 0.f); v3 = fmaxf(v3, 0.f);
                }
                fsk[cc * FS_STRIDE + r0]           = v0;
                fsk[(cc + 1) * FS_STRIDE + r0]     = v1;
                fsk[cc * FS_STRIDE + r0 + 8]       = v2;
                fsk[(cc + 1) * FS_STRIDE + r0 + 8] = v3;
            }
        }
        __syncthreads();
    }

    // ======================= phase 2 (R4-validated, 512 thr) =================

    // norms: 4 threads per row over 128 rows
    {
        int row = t >> 2, q4 = t & 3;
        float s = 0.f;
        #pragma unroll 8
        for (int i = 0; i < 64; ++i) {
            float v = fsk[(q4 * 64 + i) * FS_STRIDE + row];
            s += v * v;
        }
        s += __shfl_xor_sync(0xffffffffu, s, 1);
        s += __shfl_xor_sync(0xffffffffu, s, 2);
        if (q4 == 0) { if (row < 64) rsA[row] = s; else rsB[row - 64] = s; }
    }
    if (t < 64)       { lmq[t] = __logf(fmaxf(mq[(size_t)b * 64 + t], 1e-8f)); la[t] = 0.f; }
    else if (t < 128) { lmr[t - 64] = __logf(fmaxf(mr[(size_t)b * 64 + (t - 64)], 1e-8f)); lb[t - 64] = 0.f; }
    __syncthreads();

    // Gram: thread (gy 0..31 -> 2 k rows, gx 0..15 -> 4 m cols)
    {
        const int gx = t & 15, gy = t >> 4;
        const int k2 = 2 * gy, m4 = 4 * gx;
        unsigned long long g2[2][2];
        g2[0][0] = g2[0][1] = g2[1][0] = g2[1][1] = 0ull;
        #pragma unroll 4
        for (int d = 0; d < 256; ++d) {
            const float2 xv = *(const float2*)&fsk[d * FS_STRIDE + k2];
            const ulonglong2 yv = *(const ulonglong2*)&fsk[d * FS_STRIDE + 64 + m4];
            unsigned long long xp0 = pack2(xv.x, xv.x);
            unsigned long long xp1 = pack2(xv.y, xv.y);
            g2[0][0] = fma2(xp0, yv.x, g2[0][0]);
            g2[0][1] = fma2(xp0, yv.y, g2[0][1]);
            g2[1][0] = fma2(xp1, yv.x, g2[1][0]);
            g2[1][1] = fma2(xp1, yv.y, g2[1][1]);
        }
        #pragma unroll
        for (int kk = 0; kk < 2; ++kk) {
            int k = k2 + kk;
            float g[4];
            unpack2(g2[kk][0], g[0], g[1]);
            unpack2(g2[kk][1], g[2], g[3]);
            float nk = rsA[k];
            float lmqk = lmq[k];
            #pragma unroll
            for (int j = 0; j < 4; ++j) {
                int m = m4 + j;
                float cc = sqrtf(fmaxf(nk + rsB[m] - 2.f * g[j], 0.f));
                Cs[k * 65 + m]  = cc;
                lKs[k * 65 + m] = -cc * 20.0f + lmqk + lmr[m];
            }
        }
    }
    __syncthreads();

    // Sinkhorn: 15 iterations, 8 threads per row/col
    const int rk = t >> 3;
    const int q  = t & 7;
    for (int it = 0; it < NI_; ++it) {
        {
            float v[8], mx = -1e30f;
            #pragma unroll
            for (int j = 0; j < 8; ++j) {
                int m = q * 8 + j;
                v[j] = lKs[rk * 65 + m] + lb[m];
                mx = fmaxf(mx, v[j]);
            }
            mx = fmaxf(mx, __shfl_xor_sync(0xffffffffu, mx, 1));
            mx = fmaxf(mx, __shfl_xor_sync(0xffffffffu, mx, 2));
            mx = fmaxf(mx, __shfl_xor_sync(0xffffffffu, mx, 4));
            float s = 0.f;
            #pragma unroll
            for (int j = 0; j < 8; ++j) s += __expf(v[j] - mx);
            s += __shfl_xor_sync(0xffffffffu, s, 1);
            s += __shfl_xor_sync(0xffffffffu, s, 2);
            s += __shfl_xor_sync(0xffffffffu, s, 4);
            if (q == 0) la[rk] = -(mx + __logf(s));
        }
        __syncthreads();
        {
            float v[8], mx = -1e30f;
            #pragma unroll
            for (int j = 0; j < 8; ++j) {
                int k = q * 8 + j;
                v[j] = lKs[k * 65 + rk] + la[k];
                mx = fmaxf(mx, v[j]);
            }
            mx = fmaxf(mx, __shfl_xor_sync(0xffffffffu, mx, 1));
            mx = fmaxf(mx, __shfl_xor_sync(0xffffffffu, mx, 2));
            mx = fmaxf(mx, __shfl_xor_sync(0xffffffffu, mx, 4));
            float s = 0.f;
            #pragma unroll
            for (int j = 0; j < 8; ++j) s += __expf(v[j] - mx);
            s += __shfl_xor_sync(0xffffffffu, s, 1);
            s += __shfl_xor_sync(0xffffffffu, s, 2);
            s += __shfl_xor_sync(0xffffffffu, s, 4);
            if (q == 0) lb[rk] = -(mx + __logf(s));
        }
        __syncthreads();
    }

    // T = exp(lK + la + lb)
    {
        float lak = la[rk];
        #pragma unroll
        for (int j = 0; j < 8; ++j) {
            int m = q * 8 + j;
            Ts[rk * 65 + m] = __expf(lKs[rk * 65 + m] + lak + lb[m]);
        }
    }
    __syncthreads();

    // power iterations
    for (int it = 0; it < MI_; ++it) {
        float s = 0.f;
        #pragma unroll
        for (int j = 0; j < 8; ++j) {
            int m = q * 8 + j;
            float v = Ts[rk * 65 + m];
            v *= v;
            Ts[rk * 65 + m] = v;
            s += v;
        }
        s += __shfl_xor_sync(0xffffffffu, s, 1);
        s += __shfl_xor_sync(0xffffffffu, s, 2);
        s += __shfl_xor_sync(0xffffffffu, s, 4);
        if (q == 0) rsA[rk] = s;
        __syncthreads();
        float dn = 1.f / (rsA[rk] + 1e-8f);
        #pragma unroll
        for (int j = 0; j < 8; ++j) Ts[rk * 65 + q * 8 + j] *= dn;
        __syncthreads();
        float cs = 0.f;
        #pragma unroll
        for (int j = 0; j < 8; ++j) cs += Ts[(q * 8 + j) * 65 + rk];
        cs += __shfl_xor_sync(0xffffffffu, cs, 1);
        cs += __shfl_xor_sync(0xffffffffu, cs, 2);
        cs += __shfl_xor_sync(0xffffffffu, cs, 4);
        if (q == 0) rsB[rk] = cs;
        __syncthreads();
        #pragma unroll
        for (int j = 0; j < 8; ++j) {
            int m = q * 8 + j;
            Ts[rk * 65 + m] /= (rsB[m] + 1e-8f);
        }
        __syncthreads();
    }

    // c, sigmoid
    {
        float s = 0.f;
        #pragma unroll
        for (int j = 0; j < 8; ++j) {
            int m = q * 8 + j;
            s += Ts[rk * 65 + m] * Cs[rk * 65 + m];
        }
        red[t] = s;
        __syncthreads();
        for (int off = 256; off > 0; off >>= 1) {
            if (t < off) red[t] += red[t + off];
            __syncthreads();
        }
        if (t == 0) {
            float c = red[0];
            out_c[b] = c;
            out_sig[b] = 1.f / (1.f + __expf(c));
        }
    }

    // write T and C
    {
        int row = t >> 3;
        int cb  = (t & 7) * 8;
        float4 a4, b4;
        a4.x = Ts[row * 65 + cb + 0]; a4.y = Ts[row * 65 + cb + 1];
        a4.z = Ts[row * 65 + cb + 2]; a4.w = Ts[row * 65 + cb + 3];
        b4.x = Ts[row * 65 + cb + 4]; b4.y = Ts[row * 65 + cb + 5];
        b4.z = Ts[row * 65 + cb + 6]; b4.w = Ts[row * 65 + cb + 7];
        *(float4*)&out_T[((size_t)b * 64 + row) * 64 + cb]     = a4;
        *(float4*)&out_T[((size_t)b * 64 + row) * 64 + cb + 4] = b4;
        a4.x = Cs[row * 65 + cb + 0]; a4.y = Cs[row * 65 + cb + 1];
        a4.z = Cs[row * 65 + cb + 2]; a4.w = Cs[row * 65 + cb + 3];
        b4.x = Cs[row * 65 + cb + 4]; b4.y = Cs[row * 65 + cb + 5];
        b4.z = Cs[row * 65 + cb + 6]; b4.w = Cs[row * 65 + cb + 7];
        *(float4*)&out_C[((size_t)b * 64 + row) * 64 + cb]     = a4;
        *(float4*)&out_C[((size_t)b * 64 + row) * 64 + cb + 4] = b4;
    }
}

// ---------------------------------------------------------------------------
extern "C" void kernel_launch(void* const* d_in, const int* in_sizes, int n_in,
                              void* d_out, int out_size) {
    const float* sq = (const float*)d_in[0];
    const float* sr = (const float*)d_in[1];
    const float* mq = (const float*)d_in[2];
    const float* mr = (const float*)d_in[3];
    const float* W1 = (const float*)d_in[4];
    const float* b1 = (const float*)d_in[5];
    const float* W2 = (const float*)d_in[6];
    const float* b2 = (const float*)d_in[7];
    float* out = (float*)d_out;

    cudaFuncSetAttribute(fused_kernel, cudaFuncAttributeMaxDynamicSharedMemorySize, SMEM_BYTES);

    wprep_kernel<<<128, 256>>>(W1, W2);
    fused_kernel<<<B_, 512, SMEM_BYTES>>>(sq, sr, mq, mr, b1, b2, out);
}